// round 5
// baseline (speedup 1.0000x reference)
#include <cuda_runtime.h>

// RNN_40733469835755 — wavefront RNN, 2 timesteps/tick, 2 blocks per SM.
// B=2048, T=512, D=8, H=20, L=10. 256 blocks x 352 threads (11 warps), BQ=8.
// Warp l owns layer l (all 20 j for 8 batch rows, 1 row/lane); warp 10 = head.
// Tick s: layer l computes t = 2(s-l), 2(s-l)+1; ONE __syncthreads per tick.
// Intra-tick recurrence is warp-local (__syncwarp). ALL weights stream from
// SMEM as broadcast LDS (4 distinct addrs/warp -> 1 phase); registers kept
// under 93 so 2 blocks co-reside per SM (latency hiding via decorrelated
// blocks instead of per-warp hoisting).

#define Tn 512
#define Dn 8
#define Hn 20
#define Ln 10
#define BQ 8
#define NT 352
#define NB 256
#define ROWLEN 220
#define UPITCH (BQ * ROWLEN + 16)   // 1776 floats
#define NTICKS (Tn / 2 + Ln)        // 266

typedef unsigned long long u64;

struct __align__(16) Smem {
  float W[Ln][Hn][2 * Hn];   // concat [Wih(pad20) | Whh]
  float bsum[Ln][Hn];
  float fcw[Hn][Hn];
  float fcb[Hn];
  float l2w[Hn];
  float l2b[4];
  float A[2][2][UPITCH];     // [parity][u][row*ROWLEN + slot*20 + k]
};

__device__ __forceinline__ u64 fma2(u64 a, u64 b, u64 c) {
  u64 d;
  asm("fma.rn.f32x2 %0, %1, %2, %3;" : "=l"(d) : "l"(a), "l"(b), "l"(c));
  return d;
}
__device__ __forceinline__ float f2lo(u64 v) { return __uint_as_float((unsigned)v); }
__device__ __forceinline__ float f2hi(u64 v) { return __uint_as_float((unsigned)(v >> 32)); }

__device__ __forceinline__ float ex2a(float x) {
  float r; asm("ex2.approx.f32 %0, %1;" : "=f"(r) : "f"(x)); return r;
}
__device__ __forceinline__ float rcpa(float x) {
  float r; asm("rcp.approx.f32 %0, %1;" : "=f"(r) : "f"(x)); return r;
}
__device__ __forceinline__ float tanh_fast(float x) {
  float z = fminf(fmaxf(x, -9.0f), 9.0f);
  float e = ex2a(z * 2.8853900817779268f);  // 2*log2(e)
  return (e - 1.0f) * rcpa(e + 1.0f);
}

__global__ __launch_bounds__(NT, 2)
void rnn_kernel(const float* __restrict__ x,
                const float* __restrict__ g_wih0,
                const float* __restrict__ g_wih,
                const float* __restrict__ g_whh,
                const float* __restrict__ g_bih,
                const float* __restrict__ g_bhh,
                const float* __restrict__ g_fcw,
                const float* __restrict__ g_fcb,
                const float* __restrict__ g_l2w,
                const float* __restrict__ g_l2b,
                float* __restrict__ y) {
  extern __shared__ float smem_raw[];
  Smem* S = (Smem*)smem_raw;

  const int tid  = threadIdx.x;
  const int wid  = tid >> 5;
  const int lane = tid & 31;
  const int b0   = blockIdx.x * BQ;

  // ---- one-time init ----
  for (int i = tid; i < Ln * Hn * 2 * Hn; i += NT) {
    int k = i % (2 * Hn);
    int j = (i / (2 * Hn)) % Hn;
    int l = i / (2 * Hn * Hn);
    float v;
    if (k < Hn) {
      if (l == 0) v = (k < Dn) ? g_wih0[j * Dn + k] : 0.0f;
      else        v = g_wih[((size_t)(l - 1) * Hn + j) * Hn + k];
    } else {
      v = g_whh[((size_t)l * Hn + j) * Hn + (k - Hn)];
    }
    (&S->W[0][0][0])[i] = v;
  }
  for (int i = tid; i < Ln * Hn; i += NT) (&S->bsum[0][0])[i] = g_bih[i] + g_bhh[i];
  for (int i = tid; i < Hn * Hn; i += NT) (&S->fcw[0][0])[i] = g_fcw[i];
  if (tid < Hn) { S->fcb[tid] = g_fcb[tid]; S->l2w[tid] = g_l2w[tid]; }
  if (tid == 0) S->l2b[0] = g_l2b[0];
  for (int i = tid; i < 2 * 2 * UPITCH; i += NT) (&S->A[0][0][0])[i] = 0.0f;
  __syncthreads();
  // x[t=0] (u0) and x[t=1] (u1) into read-parity (rp=1 at tick 0).
  if (tid < 32) {
    int u = tid >> 4, row = (tid >> 1) & 7, half = tid & 1;
    float4 v = *(const float4*)&x[(((size_t)(b0 + row)) * Tn + u) * Dn + half * 4];
    *(float4*)&S->A[1][u][row * ROWLEN + half * 4] = v;
  }
  __syncthreads();

  if (wid < Ln) {
    // ================= layer warp =================
    const int l   = wid;
    const int jq  = lane >> 3;   // 0..3 -> j rows jq*5..+4
    const int bbl = lane & 7;    // batch row
    const int j5  = jq * 5;
    const float* wIn  = &S->W[l][j5][0];   // row stride 40 floats
    const float* wRec = &S->W[l][j5][Hn];
    float bj[5];
#pragma unroll
    for (int jj = 0; jj < 5; ++jj) bj[jj] = S->bsum[l][j5 + jj];
    const int rr = bbl * ROWLEN;

    for (int s = 0; s < NTICKS; ++s) {
      const int wp = s & 1, rp = wp ^ 1;
      const int t0 = 2 * (s - l);
      if (t0 >= 0 && t0 < Tn) {
        const float* Ar0 = S->A[rp][0] + rr;
        const float* Ar1 = S->A[rp][1] + rr;
        float* Aw0 = S->A[wp][0] + rr;
        float* Aw1 = S->A[wp][1] + rr;
        u64 a[5], c[5];
#pragma unroll
        for (int jj = 0; jj < 5; ++jj) { a[jj] = 0; c[jj] = 0; }

        // rec tau0: h[l][t0-1] = prev tick's tau1 output
        {
          const float* pr = Ar1 + (l + 1) * Hn;
#pragma unroll
          for (int kc = 0; kc < 5; ++kc) {
            ulonglong2 v = *(const ulonglong2*)(pr + kc * 4);
#pragma unroll
            for (int jj = 0; jj < 5; ++jj) {
              ulonglong2 w = *(const ulonglong2*)(wRec + jj * 2 * Hn + kc * 4);
              a[jj] = fma2(w.x, v.x, fma2(w.y, v.y, a[jj]));
            }
          }
        }
        // input parts, both timesteps (weights loaded once, reused 2x)
        {
          const float* q0 = Ar0 + l * Hn;
          const float* q1 = Ar1 + l * Hn;
#pragma unroll
          for (int kc = 0; kc < 5; ++kc) {
            ulonglong2 v0 = *(const ulonglong2*)(q0 + kc * 4);
            ulonglong2 v1 = *(const ulonglong2*)(q1 + kc * 4);
#pragma unroll
            for (int jj = 0; jj < 5; ++jj) {
              ulonglong2 w = *(const ulonglong2*)(wIn + jj * 2 * Hn + kc * 4);
              a[jj] = fma2(w.x, v0.x, fma2(w.y, v0.y, a[jj]));
              c[jj] = fma2(w.x, v1.x, fma2(w.y, v1.y, c[jj]));
            }
          }
        }
        // finish tau0, publish (consumers are warp-local)
        {
          float* o0 = Aw0 + (l + 1) * Hn + j5;
#pragma unroll
          for (int jj = 0; jj < 5; ++jj)
            o0[jj] = tanh_fast(f2lo(a[jj]) + f2hi(a[jj]) + bj[jj]);
        }
        __syncwarp();
        // rec tau1: reads tau0 output just written by this warp
        {
          const float* ps = Aw0 + (l + 1) * Hn;
#pragma unroll
          for (int kc = 0; kc < 5; ++kc) {
            ulonglong2 v = *(const ulonglong2*)(ps + kc * 4);
#pragma unroll
            for (int jj = 0; jj < 5; ++jj) {
              ulonglong2 w = *(const ulonglong2*)(wRec + jj * 2 * Hn + kc * 4);
              c[jj] = fma2(w.x, v.x, fma2(w.y, v.y, c[jj]));
            }
          }
          float* o1 = Aw1 + (l + 1) * Hn + j5;
#pragma unroll
          for (int jj = 0; jj < 5; ++jj)
            o1[jj] = tanh_fast(f2lo(c[jj]) + f2hi(c[jj]) + bj[jj]);
        }
      }
      __syncthreads();
    }
  } else {
    // ================= head warp =================
    const int u  = lane >> 4;        // timestep within tick
    const int jh = (lane >> 3) & 1;  // fc rows jh*10..+9
    const int b8 = lane & 7;         // batch row
    const int xu = lane >> 4, xrow = (lane >> 1) & 7, xhalf = lane & 1;

    for (int s = 0; s < NTICKS; ++s) {
      const int wp = s & 1, rp = wp ^ 1;
      // prefetch x[t = 2(s+1)+u] into write parity, plane u
      const int tx = 2 * (s + 1) + xu;
      if (tx < Tn) {
        float4 v = *(const float4*)&x[(((size_t)(b0 + xrow)) * Tn + tx) * Dn + xhalf * 4];
        *(float4*)&S->A[wp][xu][xrow * ROWLEN + xhalf * 4] = v;
      }
      if (s >= Ln) {
        const int t = 2 * (s - Ln) + u;
        const float* hrow = S->A[rp][u] + b8 * ROWLEN + Ln * Hn;  // slot 10
        ulonglong2 hv[5];
#pragma unroll
        for (int kc = 0; kc < 5; ++kc) hv[kc] = *(const ulonglong2*)(hrow + kc * 4);
        float p = 0.0f;
#pragma unroll
        for (int jj = 0; jj < 10; ++jj) {
          int j = jh * 10 + jj;
          const float* wr = &S->fcw[j][0];
          u64 d0 = 0, d1 = 0;
#pragma unroll
          for (int kc = 0; kc < 5; ++kc) {
            ulonglong2 w = *(const ulonglong2*)(wr + kc * 4);
            d0 = fma2(w.x, hv[kc].x, d0);
            d1 = fma2(w.y, hv[kc].y, d1);
          }
          float v = f2lo(d0) + f2hi(d0) + f2lo(d1) + f2hi(d1) + S->fcb[j];
          p += fmaxf(v, 0.0f) * S->l2w[j];
        }
        p += __shfl_xor_sync(0xFFFFFFFFu, p, 8);  // reduce over jh
        if (jh == 0)
          y[(size_t)(b0 + b8) * Tn + t] = p + S->l2b[0];
      }
      __syncthreads();
    }
  }
}

extern "C" void kernel_launch(void* const* d_in, const int* in_sizes, int n_in,
                              void* d_out, int out_size) {
  (void)in_sizes; (void)n_in; (void)out_size;
  const float* x    = (const float*)d_in[0];
  const float* wih0 = (const float*)d_in[1];
  const float* wih  = (const float*)d_in[2];
  const float* whh  = (const float*)d_in[3];
  const float* bih  = (const float*)d_in[4];
  const float* bhh  = (const float*)d_in[5];
  const float* fcw  = (const float*)d_in[6];
  const float* fcb  = (const float*)d_in[7];
  const float* l2w  = (const float*)d_in[8];
  const float* l2b  = (const float*)d_in[9];
  float* y = (float*)d_out;

  cudaFuncSetAttribute(rnn_kernel, cudaFuncAttributeMaxDynamicSharedMemorySize,
                       (int)sizeof(Smem));
  rnn_kernel<<<NB, NT, sizeof(Smem)>>>(x, wih0, wih, whh, bih, bhh,
                                       fcw, fcb, l2w, l2b, y);
}

// round 7
// speedup vs baseline: 1.0729x; 1.0729x over previous
#include <cuda_runtime.h>

// RNN_40733469835755 — wavefront RNN, 4 timesteps/tick, 2 blocks per SM.
// B=2048, T=512, D=8, H=20, L=10. 256 blocks x 352 threads (11 warps), BQ=8.
// Warp l owns layer l; tick s processes t = 4(s-l)..4(s-l)+3; ONE __syncthreads
// per tick, NTICKS=138. Lane=(jq 0..3, bb 0..7): 5 j-rows x 1 batch row x
// 4 steps = 20 outputs/lane/tick (input weights amortized 4x). Intra-tick
// recurrence is warp-local (__syncwarp). All weights stream from SMEM as
// broadcast LDS; regs kept <=90 so 2 blocks/SM co-reside (grid 256 > 148 SMs
// -> every SM busy, de-phased blocks hide each other's latency).

#define Tn 512
#define Dn 8
#define Hn 20
#define Ln 10
#define Un 4
#define BQ 8
#define NT 352
#define NB 256
#define ROWLEN 220
#define UPITCH (BQ * ROWLEN + 16)   // 1776 floats per (parity,u) plane
#define NTICKS (Tn / Un + Ln)       // 138

typedef unsigned long long u64;

struct __align__(16) Smem {
  float W[Ln][Hn][2 * Hn];   // concat [Wih(pad20) | Whh]
  float bsum[Ln][Hn];
  float fcw[Hn][Hn];
  float fcb[Hn];
  float l2w[Hn];
  float l2b[4];
  float A[2][Un][UPITCH];    // [parity][u][row*ROWLEN + slot*20 + k]
};

__device__ __forceinline__ u64 fma2(u64 a, u64 b, u64 c) {
  u64 d;
  asm("fma.rn.f32x2 %0, %1, %2, %3;" : "=l"(d) : "l"(a), "l"(b), "l"(c));
  return d;
}
__device__ __forceinline__ float f2lo(u64 v) { return __uint_as_float((unsigned)v); }
__device__ __forceinline__ float f2hi(u64 v) { return __uint_as_float((unsigned)(v >> 32)); }

__device__ __forceinline__ float ex2a(float x) {
  float r; asm("ex2.approx.f32 %0, %1;" : "=f"(r) : "f"(x)); return r;
}
__device__ __forceinline__ float rcpa(float x) {
  float r; asm("rcp.approx.f32 %0, %1;" : "=f"(r) : "f"(x)); return r;
}
__device__ __forceinline__ float tanh_fast(float x) {
  float z = fminf(fmaxf(x, -9.0f), 9.0f);
  float e = ex2a(z * 2.8853900817779268f);  // 2*log2(e)
  return (e - 1.0f) * rcpa(e + 1.0f);
}

__global__ __launch_bounds__(NT, 2)
void rnn_kernel(const float* __restrict__ x,
                const float* __restrict__ g_wih0,
                const float* __restrict__ g_wih,
                const float* __restrict__ g_whh,
                const float* __restrict__ g_bih,
                const float* __restrict__ g_bhh,
                const float* __restrict__ g_fcw,
                const float* __restrict__ g_fcb,
                const float* __restrict__ g_l2w,
                const float* __restrict__ g_l2b,
                float* __restrict__ y) {
  extern __shared__ float smem_raw[];
  Smem* S = (Smem*)smem_raw;

  const int tid  = threadIdx.x;
  const int wid  = tid >> 5;
  const int lane = tid & 31;
  const int b0   = blockIdx.x * BQ;

  // ---- one-time init ----
  for (int i = tid; i < Ln * Hn * 2 * Hn; i += NT) {
    int k = i % (2 * Hn);
    int j = (i / (2 * Hn)) % Hn;
    int l = i / (2 * Hn * Hn);
    float v;
    if (k < Hn) {
      if (l == 0) v = (k < Dn) ? g_wih0[j * Dn + k] : 0.0f;
      else        v = g_wih[((size_t)(l - 1) * Hn + j) * Hn + k];
    } else {
      v = g_whh[((size_t)l * Hn + j) * Hn + (k - Hn)];
    }
    (&S->W[0][0][0])[i] = v;
  }
  for (int i = tid; i < Ln * Hn; i += NT) (&S->bsum[0][0])[i] = g_bih[i] + g_bhh[i];
  for (int i = tid; i < Hn * Hn; i += NT) (&S->fcw[0][0])[i] = g_fcw[i];
  if (tid < Hn) { S->fcb[tid] = g_fcb[tid]; S->l2w[tid] = g_l2w[tid]; }
  if (tid == 0) S->l2b[0] = g_l2b[0];
  for (int i = tid; i < 2 * Un * UPITCH; i += NT) (&S->A[0][0][0])[i] = 0.0f;
  __syncthreads();
  // x[t=0..3] into parity 1 (read parity at tick 0), planes u=0..3.
  if (tid < 64) {
    int row = tid >> 3, tt = (tid >> 1) & 3, half = tid & 1;
    float4 v = *(const float4*)&x[(((size_t)(b0 + row)) * Tn + tt) * Dn + half * 4];
    *(float4*)&S->A[1][tt][row * ROWLEN + half * 4] = v;
  }
  __syncthreads();

  if (wid < Ln) {
    // ================= layer warp =================
    const int l  = wid;
    const int jq = lane >> 3;   // 0..3 -> j rows jq*5..+4
    const int bb = lane & 7;    // batch row
    const int j5 = jq * 5;
    const float* wIn  = &S->W[l][j5][0];   // row stride 40 floats
    const float* wRec = &S->W[l][j5][Hn];
    float bj[5];
#pragma unroll
    for (int jj = 0; jj < 5; ++jj) bj[jj] = S->bsum[l][j5 + jj];
    const int rr = bb * ROWLEN;

    for (int s = 0; s < NTICKS; ++s) {
      const int wp = s & 1, rp = wp ^ 1;
      const int t0 = Un * (s - l);
      if (t0 >= 0 && t0 < Tn) {
        // ---- phase 1: input parts for all 4 steps (wIn loaded once) ----
        u64 acc[Un][5];
#pragma unroll
        for (int u = 0; u < Un; ++u)
#pragma unroll
          for (int jj = 0; jj < 5; ++jj) acc[u][jj] = 0;
#pragma unroll
        for (int kc = 0; kc < 5; ++kc) {
          ulonglong2 xv[Un];
#pragma unroll
          for (int u = 0; u < Un; ++u)
            xv[u] = *(const ulonglong2*)(S->A[rp][u] + rr + l * Hn + kc * 4);
#pragma unroll
          for (int jj = 0; jj < 5; ++jj) {
            ulonglong2 w = *(const ulonglong2*)(wIn + jj * 2 * Hn + kc * 4);
#pragma unroll
            for (int u = 0; u < Un; ++u)
              acc[u][jj] = fma2(w.x, xv[u].x, fma2(w.y, xv[u].y, acc[u][jj]));
          }
        }
        // ---- phase 2: serial recurrence over the 4 steps ----
        const float* hprev = S->A[rp][Un - 1] + rr + (l + 1) * Hn;  // h[t0-1]
#pragma unroll
        for (int u = 0; u < Un; ++u) {
#pragma unroll
          for (int kc = 0; kc < 5; ++kc) {
            ulonglong2 hv = *(const ulonglong2*)(hprev + kc * 4);
#pragma unroll
            for (int jj = 0; jj < 5; ++jj) {
              ulonglong2 w = *(const ulonglong2*)(wRec + jj * 2 * Hn + kc * 4);
              acc[u][jj] = fma2(w.x, hv.x, fma2(w.y, hv.y, acc[u][jj]));
            }
          }
          float* o = S->A[wp][u] + rr + (l + 1) * Hn + j5;
#pragma unroll
          for (int jj = 0; jj < 5; ++jj)
            o[jj] = tanh_fast(f2lo(acc[u][jj]) + f2hi(acc[u][jj]) + bj[jj]);
          __syncwarp();
          hprev = S->A[wp][u] + rr + (l + 1) * Hn;
        }
      }
      __syncthreads();
    }
  } else {
    // ================= head warp =================
    const int u  = lane >> 3;   // timestep within tick
    const int bb = lane & 7;    // batch row

    for (int s = 0; s < NTICKS; ++s) {
      const int wp = s & 1, rp = wp ^ 1;
      // prefetch x for tick s+1 (t = 4(s+1)..+3) into write parity
      const int txb = Un * (s + 1);
      if (txb < Tn) {
#pragma unroll
        for (int i = 0; i < 2; ++i) {
          int unit = lane + 32 * i;
          int row = unit >> 3, tt = (unit >> 1) & 3, half = unit & 1;
          float4 v = *(const float4*)&x[(((size_t)(b0 + row)) * Tn + txb + tt) * Dn + half * 4];
          *(float4*)&S->A[wp][tt][row * ROWLEN + half * 4] = v;
        }
      }
      if (s >= Ln) {
        const int t = Un * (s - Ln) + u;
        const float* hrow = S->A[rp][u] + bb * ROWLEN + Ln * Hn;  // slot 10
        ulonglong2 hv[5];
#pragma unroll
        for (int kc = 0; kc < 5; ++kc) hv[kc] = *(const ulonglong2*)(hrow + kc * 4);
        float p = 0.0f;
#pragma unroll
        for (int j = 0; j < Hn; ++j) {
          const float* wr = &S->fcw[j][0];
          u64 d0 = 0, d1 = 0;
#pragma unroll
          for (int kc = 0; kc < 5; ++kc) {
            ulonglong2 w = *(const ulonglong2*)(wr + kc * 4);
            d0 = fma2(w.x, hv[kc].x, d0);
            d1 = fma2(w.y, hv[kc].y, d1);
          }
          float v = f2lo(d0) + f2hi(d0) + f2lo(d1) + f2hi(d1) + S->fcb[j];
          p += fmaxf(v, 0.0f) * S->l2w[j];
        }
        y[(size_t)(b0 + bb) * Tn + t] = p + S->l2b[0];
      }
      __syncthreads();
    }
  }
}

extern "C" void kernel_launch(void* const* d_in, const int* in_sizes, int n_in,
                              void* d_out, int out_size) {
  (void)in_sizes; (void)n_in; (void)out_size;
  const float* x    = (const float*)d_in[0];
  const float* wih0 = (const float*)d_in[1];
  const float* wih  = (const float*)d_in[2];
  const float* whh  = (const float*)d_in[3];
  const float* bih  = (const float*)d_in[4];
  const float* bhh  = (const float*)d_in[5];
  const float* fcw  = (const float*)d_in[6];
  const float* fcb  = (const float*)d_in[7];
  const float* l2w  = (const float*)d_in[8];
  const float* l2b  = (const float*)d_in[9];
  float* y = (float*)d_out;

  cudaFuncSetAttribute(rnn_kernel, cudaFuncAttributeMaxDynamicSharedMemorySize,
                       (int)sizeof(Smem));
  rnn_kernel<<<NB, NT, sizeof(Smem)>>>(x, wih0, wih, whh, bih, bhh,
                                       fcw, fcb, l2w, l2b, y);
}

// round 8
// speedup vs baseline: 1.1466x; 1.0687x over previous
#include <cuda_runtime.h>

// RNN_40733469835755 — wavefront RNN, Un=4 timesteps/tick, reg-hoisted wRec.
// B=2048, T=512, D=8, H=20, L=10. 128 blocks x 352 threads (11 warps), BQ=16.
// Warp l owns layer l: lane=(jq 0..3, bb 0..7) -> 5 j x 2 rows x 4 steps =
// 40 outputs/lane/tick. Tick s: t = 4(s-l)..+3; ONE __syncthreads per tick,
// NTICKS=138. Recurrent weights + biases in registers; input weights streamed
// from SMEM twice per tick (u-pairs) so live accumulators stay at 20 u64.
// Warp 10 = MLP head (2u x 2rows x 10j per lane, ~400 fma2 = layer-balanced)
// + x prefetch + y store. tanh = ex2+rcp, no clamp (|preact| << 44).

#define Tn 512
#define Dn 8
#define Hn 20
#define Ln 10
#define Un 4
#define BQ 16
#define NT 352
#define NB 128
#define ROWLEN 220
#define UPITCH (BQ * ROWLEN + 16)   // 3536 floats per (parity,u) plane
#define NTICKS (Tn / Un + Ln)       // 138

typedef unsigned long long u64;

struct __align__(16) Smem {
  float W[Ln][Hn][2 * Hn];   // concat [Wih(pad20) | Whh]
  float bsum[Ln][Hn];
  float fcw[Hn][Hn];
  float fcb[Hn];
  float l2w[Hn];
  float l2b[4];
  float A[2][Un][UPITCH];    // [parity][u][row*ROWLEN + slot*20 + k]
};

__device__ __forceinline__ u64 fma2(u64 a, u64 b, u64 c) {
  u64 d;
  asm("fma.rn.f32x2 %0, %1, %2, %3;" : "=l"(d) : "l"(a), "l"(b), "l"(c));
  return d;
}
__device__ __forceinline__ float f2lo(u64 v) { return __uint_as_float((unsigned)v); }
__device__ __forceinline__ float f2hi(u64 v) { return __uint_as_float((unsigned)(v >> 32)); }

__device__ __forceinline__ float ex2a(float x) {
  float r; asm("ex2.approx.f32 %0, %1;" : "=f"(r) : "f"(x)); return r;
}
__device__ __forceinline__ float rcpa(float x) {
  float r; asm("rcp.approx.f32 %0, %1;" : "=f"(r) : "f"(x)); return r;
}
// tanh(x) = (e^{2x}-1)/(e^{2x}+1). No clamp: |preact| <= ~15 here, overflow
// needs |x| > 44. ex2/rcp approx err ~1e-7 rel.
__device__ __forceinline__ float tanh_fast(float x) {
  float e = ex2a(x * 2.8853900817779268f);  // 2*log2(e)
  return (e - 1.0f) * rcpa(e + 1.0f);
}

__global__ __launch_bounds__(NT, 1)
void rnn_kernel(const float* __restrict__ x,
                const float* __restrict__ g_wih0,
                const float* __restrict__ g_wih,
                const float* __restrict__ g_whh,
                const float* __restrict__ g_bih,
                const float* __restrict__ g_bhh,
                const float* __restrict__ g_fcw,
                const float* __restrict__ g_fcb,
                const float* __restrict__ g_l2w,
                const float* __restrict__ g_l2b,
                float* __restrict__ y) {
  extern __shared__ float smem_raw[];
  Smem* S = (Smem*)smem_raw;

  const int tid  = threadIdx.x;
  const int wid  = tid >> 5;
  const int lane = tid & 31;
  const int b0   = blockIdx.x * BQ;

  // ---- one-time init ----
  for (int i = tid; i < Ln * Hn * 2 * Hn; i += NT) {
    int k = i % (2 * Hn);
    int j = (i / (2 * Hn)) % Hn;
    int l = i / (2 * Hn * Hn);
    float v;
    if (k < Hn) {
      if (l == 0) v = (k < Dn) ? g_wih0[j * Dn + k] : 0.0f;
      else        v = g_wih[((size_t)(l - 1) * Hn + j) * Hn + k];
    } else {
      v = g_whh[((size_t)l * Hn + j) * Hn + (k - Hn)];
    }
    (&S->W[0][0][0])[i] = v;
  }
  for (int i = tid; i < Ln * Hn; i += NT) (&S->bsum[0][0])[i] = g_bih[i] + g_bhh[i];
  for (int i = tid; i < Hn * Hn; i += NT) (&S->fcw[0][0])[i] = g_fcw[i];
  if (tid < Hn) { S->fcb[tid] = g_fcb[tid]; S->l2w[tid] = g_l2w[tid]; }
  if (tid == 0) S->l2b[0] = g_l2b[0];
  for (int i = tid; i < 2 * Un * UPITCH; i += NT) (&S->A[0][0][0])[i] = 0.0f;
  __syncthreads();
  // x[t=0..3] into parity 1 (read parity of tick 0), planes u=0..3.
  // unit bits: b0=half, b1-2=tt, b3-6=row -> 128 units.
  if (tid < 128) {
    int row = tid >> 3, tt = (tid >> 1) & 3, half = tid & 1;
    float4 v = *(const float4*)&x[(((size_t)(b0 + row)) * Tn + tt) * Dn + half * 4];
    *(float4*)&S->A[1][tt][row * ROWLEN + half * 4] = v;
  }
  __syncthreads();

  if (wid < Ln) {
    // ================= layer warp =================
    const int l   = wid;
    const int jq  = lane >> 3;   // 0..3 -> j rows jq*5..+4
    const int bbl = lane & 7;    // batch rows bbl, bbl+8
    const int j5  = jq * 5;
    const float* wIn = &S->W[l][j5][0];   // row stride 40 floats
    const int r0 = bbl * ROWLEN, r1 = (bbl + 8) * ROWLEN;

    // hoist recurrent weights + bias into registers (per-warp invariant)
    ulonglong2 wr[5][5];
    float bj[5];
#pragma unroll
    for (int jj = 0; jj < 5; ++jj) {
      bj[jj] = S->bsum[l][j5 + jj];
#pragma unroll
      for (int kc = 0; kc < 5; ++kc)
        wr[jj][kc] = *(const ulonglong2*)(&S->W[l][j5 + jj][Hn] + kc * 4);
    }

    for (int s = 0; s < NTICKS; ++s) {
      const int wp = s & 1, rp = wp ^ 1;
      const int t0 = Un * (s - l);
      if (t0 >= 0 && t0 < Tn) {
        // h[t0-1] = prev tick's u3 output
        const float* hp0 = S->A[rp][Un - 1] + r0 + (l + 1) * Hn;
        const float* hp1 = S->A[rp][Un - 1] + r1 + (l + 1) * Hn;
#pragma unroll
        for (int up = 0; up < Un; up += 2) {
          u64 acc[2][2][5];   // [uu][row][jj]
#pragma unroll
          for (int uu = 0; uu < 2; ++uu)
#pragma unroll
            for (int r = 0; r < 2; ++r)
#pragma unroll
              for (int jj = 0; jj < 5; ++jj) acc[uu][r][jj] = 0;

          // input parts for u = up, up+1 (wIn streamed once per pair)
          const float* q00 = S->A[rp][up] + r0 + l * Hn;
          const float* q01 = S->A[rp][up] + r1 + l * Hn;
          const float* q10 = S->A[rp][up + 1] + r0 + l * Hn;
          const float* q11 = S->A[rp][up + 1] + r1 + l * Hn;
#pragma unroll
          for (int kc = 0; kc < 5; ++kc) {
            ulonglong2 x00 = *(const ulonglong2*)(q00 + kc * 4);
            ulonglong2 x01 = *(const ulonglong2*)(q01 + kc * 4);
            ulonglong2 x10 = *(const ulonglong2*)(q10 + kc * 4);
            ulonglong2 x11 = *(const ulonglong2*)(q11 + kc * 4);
#pragma unroll
            for (int jj = 0; jj < 5; ++jj) {
              ulonglong2 w = *(const ulonglong2*)(wIn + jj * 2 * Hn + kc * 4);
              acc[0][0][jj] = fma2(w.x, x00.x, fma2(w.y, x00.y, acc[0][0][jj]));
              acc[0][1][jj] = fma2(w.x, x01.x, fma2(w.y, x01.y, acc[0][1][jj]));
              acc[1][0][jj] = fma2(w.x, x10.x, fma2(w.y, x10.y, acc[1][0][jj]));
              acc[1][1][jj] = fma2(w.x, x11.x, fma2(w.y, x11.y, acc[1][1][jj]));
            }
          }
          // serial recurrence + tanh for the pair
#pragma unroll
          for (int uu = 0; uu < 2; ++uu) {
            const int u = up + uu;
#pragma unroll
            for (int kc = 0; kc < 5; ++kc) {
              ulonglong2 h0 = *(const ulonglong2*)(hp0 + kc * 4);
              ulonglong2 h1 = *(const ulonglong2*)(hp1 + kc * 4);
#pragma unroll
              for (int jj = 0; jj < 5; ++jj) {
                acc[uu][0][jj] = fma2(wr[jj][kc].x, h0.x, fma2(wr[jj][kc].y, h0.y, acc[uu][0][jj]));
                acc[uu][1][jj] = fma2(wr[jj][kc].x, h1.x, fma2(wr[jj][kc].y, h1.y, acc[uu][1][jj]));
              }
            }
            float* o0 = S->A[wp][u] + r0 + (l + 1) * Hn + j5;
            float* o1 = S->A[wp][u] + r1 + (l + 1) * Hn + j5;
#pragma unroll
            for (int jj = 0; jj < 5; ++jj) {
              o0[jj] = tanh_fast(f2lo(acc[uu][0][jj]) + f2hi(acc[uu][0][jj]) + bj[jj]);
              o1[jj] = tanh_fast(f2lo(acc[uu][1][jj]) + f2hi(acc[uu][1][jj]) + bj[jj]);
            }
            __syncwarp();
            hp0 = S->A[wp][u] + r0 + (l + 1) * Hn;
            hp1 = S->A[wp][u] + r1 + (l + 1) * Hn;
          }
        }
      }
      __syncthreads();
    }
  } else {
    // ================= head warp =================
    // lane bits: b0-2 = b8 (rows b8, b8+8), b3 = jq2 (j half), b4 = uh (u, u+2)
    const int b8  = lane & 7;
    const int jq2 = (lane >> 3) & 1;
    const int uh  = lane >> 4;

    for (int s = 0; s < NTICKS; ++s) {
      const int wp = s & 1, rp = wp ^ 1;
      // prefetch x for tick s+1 (t = 4(s+1)..+3) into write parity, slot 0
      const int txb = Un * (s + 1);
      if (txb < Tn) {
#pragma unroll
        for (int i = 0; i < 4; ++i) {
          int unit = lane + 32 * i;
          int row = unit >> 3, tt = (unit >> 1) & 3, half = unit & 1;
          float4 v = *(const float4*)&x[(((size_t)(b0 + row)) * Tn + txb + tt) * Dn + half * 4];
          *(float4*)&S->A[wp][tt][row * ROWLEN + half * 4] = v;
        }
      }
      if (s >= Ln) {
        // load top-layer h for (u in {uh, uh+2}) x (rows b8, b8+8)
        ulonglong2 hv[2][2][5];
#pragma unroll
        for (int uu = 0; uu < 2; ++uu) {
          const int u = uh + 2 * uu;
          const float* p0 = S->A[rp][u] + b8 * ROWLEN + Ln * Hn;
          const float* p1 = S->A[rp][u] + (b8 + 8) * ROWLEN + Ln * Hn;
#pragma unroll
          for (int kc = 0; kc < 5; ++kc) {
            hv[uu][0][kc] = *(const ulonglong2*)(p0 + kc * 4);
            hv[uu][1][kc] = *(const ulonglong2*)(p1 + kc * 4);
          }
        }
        float ps[2][2] = {{0.0f, 0.0f}, {0.0f, 0.0f}};
#pragma unroll
        for (int jj = 0; jj < 10; ++jj) {
          const int j = jq2 * 10 + jj;
          const float* wrow = &S->fcw[j][0];
          u64 d[2][2] = {{0, 0}, {0, 0}};
#pragma unroll
          for (int kc = 0; kc < 5; ++kc) {
            ulonglong2 w = *(const ulonglong2*)(wrow + kc * 4);
#pragma unroll
            for (int uu = 0; uu < 2; ++uu) {
              d[uu][0] = fma2(w.x, hv[uu][0][kc].x, fma2(w.y, hv[uu][0][kc].y, d[uu][0]));
              d[uu][1] = fma2(w.x, hv[uu][1][kc].x, fma2(w.y, hv[uu][1][kc].y, d[uu][1]));
            }
          }
          float fb = S->fcb[j], lw = S->l2w[j];
#pragma unroll
          for (int uu = 0; uu < 2; ++uu) {
            float v0 = f2lo(d[uu][0]) + f2hi(d[uu][0]) + fb;
            float v1 = f2lo(d[uu][1]) + f2hi(d[uu][1]) + fb;
            ps[uu][0] += fmaxf(v0, 0.0f) * lw;
            ps[uu][1] += fmaxf(v1, 0.0f) * lw;
          }
        }
        // reduce over jq2 (bit 3)
#pragma unroll
        for (int uu = 0; uu < 2; ++uu) {
          ps[uu][0] += __shfl_xor_sync(0xFFFFFFFFu, ps[uu][0], 8);
          ps[uu][1] += __shfl_xor_sync(0xFFFFFFFFu, ps[uu][1], 8);
        }
        if (jq2 == 0) {
          const float l2b0 = S->l2b[0];
#pragma unroll
          for (int uu = 0; uu < 2; ++uu) {
            const int t = Un * (s - Ln) + uh + 2 * uu;
            y[(size_t)(b0 + b8) * Tn + t]     = ps[uu][0] + l2b0;
            y[(size_t)(b0 + b8 + 8) * Tn + t] = ps[uu][1] + l2b0;
          }
        }
      }
      __syncthreads();
    }
  }
}

extern "C" void kernel_launch(void* const* d_in, const int* in_sizes, int n_in,
                              void* d_out, int out_size) {
  (void)in_sizes; (void)n_in; (void)out_size;
  const float* x    = (const float*)d_in[0];
  const float* wih0 = (const float*)d_in[1];
  const float* wih  = (const float*)d_in[2];
  const float* whh  = (const float*)d_in[3];
  const float* bih  = (const float*)d_in[4];
  const float* bhh  = (const float*)d_in[5];
  const float* fcw  = (const float*)d_in[6];
  const float* fcb  = (const float*)d_in[7];
  const float* l2w  = (const float*)d_in[8];
  const float* l2b  = (const float*)d_in[9];
  float* y = (float*)d_out;

  cudaFuncSetAttribute(rnn_kernel, cudaFuncAttributeMaxDynamicSharedMemorySize,
                       (int)sizeof(Smem));
  rnn_kernel<<<NB, NT, sizeof(Smem)>>>(x, wih0, wih, whh, bih, bhh,
                                       fcw, fcb, l2w, l2b, y);
}